// round 3
// baseline (speedup 1.0000x reference)
#include <cuda_runtime.h>
#include <math.h>

#define HB 1024          // NUM_BASIC
#define HM 8192          // NUM_MIXED
#define TT 15            // 2*CLIP_LEN-1
#define RDIM 735         // TT*7*7
#define RPAD 768
#define NN 57
#define OUT_PER_J 3249   // 57*57

// Scratch (static device globals — allocation-free)
__device__ float g_X[RPAD * HB];   // X rows, tf32-rounded, padded rows zeroed
__device__ float g_W[HM * HB];     // W, tf32-rounded
__device__ float g_Y[HM * RPAD];   // relu(X @ W^T + b), per-j rows

__device__ __forceinline__ float to_tf32(float x) {
    unsigned u;
    asm("cvt.rna.tf32.f32 %0, %1;" : "=r"(u) : "f"(x));
    return __uint_as_float(u);
}

// ---------------------------------------------------------------------------
// Kernel 1: build X[r,h] = (1+sigmoid(te[h,t])) * relu(mat[h,n,m]), tf32-rounded
//   r = t*49 + m*7 + n
// ---------------------------------------------------------------------------
__global__ void build_x(const float* __restrict__ mat, const float* __restrict__ te) {
    int idx = blockIdx.x * 256 + threadIdx.x;   // idx = r*1024 + h, grid covers RPAD*HB
    int r = idx >> 10;
    int h = idx & 1023;
    float v = 0.f;
    if (r < RDIM) {
        int t = r / 49;
        int rem = r - t * 49;
        int m = rem / 7;
        int n = rem - m * 7;
        float a = mat[h * 49 + n * 7 + m];
        if (a > 0.f) {
            float s = 1.f + 1.f / (1.f + expf(-te[h * TT + t]));
            v = to_tf32(s * a);
        }
    }
    g_X[idx] = v;
}

// ---------------------------------------------------------------------------
// Kernel 2: round W to tf32 (RN) into scratch
// ---------------------------------------------------------------------------
__global__ void round_w(const float* __restrict__ W) {
    int idx = blockIdx.x * 256 + threadIdx.x;   // float4 index, grid = HM*HB/4/256
    float4 v = reinterpret_cast<const float4*>(W)[idx];
    v.x = to_tf32(v.x);
    v.y = to_tf32(v.y);
    v.z = to_tf32(v.z);
    v.w = to_tf32(v.w);
    reinterpret_cast<float4*>(g_W)[idx] = v;
}

// ---------------------------------------------------------------------------
// Kernel 3: GEMM  Y[j, r] = relu( sum_h W[j,h]*X[r,h] + b[j] )
//   M = 8192 (j, tiles of 128), N = 768 (r, tiles of 128), K = 1024 (BK=32)
//   mma.sync.m16n8k8 tf32. 8 warps: 4 (j) x 2 (r), warp tile 32x64.
// ---------------------------------------------------------------------------
__global__ void __launch_bounds__(256, 2) gemm_k(const float* __restrict__ bias) {
    __shared__ float As[128][36];   // W tile: j-row x k  (pad 36 -> conflict-free frags)
    __shared__ float Bs[128][36];   // X tile: r-row x k

    int tid  = threadIdx.x;
    int lane = tid & 31;
    int warp = tid >> 5;
    int wj = warp >> 1;             // 0..3
    int wr = warp & 1;              // 0..1
    int jt = blockIdx.y;            // 0..63
    int rt = blockIdx.x;            // 0..5

    const float* Wg = g_W + (size_t)(jt * 128) * HB;
    const float* Xg = g_X + (size_t)(rt * 128) * HB;

    float acc[2][8][4];
    #pragma unroll
    for (int mi = 0; mi < 2; ++mi)
        #pragma unroll
        for (int ni = 0; ni < 8; ++ni)
            #pragma unroll
            for (int e = 0; e < 4; ++e) acc[mi][ni][e] = 0.f;

    for (int kc = 0; kc < HB; kc += 32) {
        __syncthreads();
        #pragma unroll
        for (int it = 0; it < 4; ++it) {
            int idx = tid + it * 256;          // 0..1023
            int row = idx >> 3;
            int c4  = (idx & 7) << 2;
            *(float4*)&As[row][c4] = *(const float4*)(Wg + (size_t)row * HB + kc + c4);
            *(float4*)&Bs[row][c4] = *(const float4*)(Xg + (size_t)row * HB + kc + c4);
        }
        __syncthreads();

        #pragma unroll
        for (int k8 = 0; k8 < 4; ++k8) {
            int kb = k8 * 8;
            int ar = wj * 32 + (lane >> 2);
            int ac = kb + (lane & 3);
            unsigned a[2][4];
            #pragma unroll
            for (int mi = 0; mi < 2; ++mi) {
                a[mi][0] = __float_as_uint(As[ar + mi * 16    ][ac    ]);
                a[mi][1] = __float_as_uint(As[ar + mi * 16 + 8][ac    ]);
                a[mi][2] = __float_as_uint(As[ar + mi * 16    ][ac + 4]);
                a[mi][3] = __float_as_uint(As[ar + mi * 16 + 8][ac + 4]);
            }
            int br = wr * 64 + (lane >> 2);
            #pragma unroll
            for (int ni = 0; ni < 8; ++ni) {
                unsigned b0 = __float_as_uint(Bs[br + ni * 8][ac    ]);
                unsigned b1 = __float_as_uint(Bs[br + ni * 8][ac + 4]);
                #pragma unroll
                for (int mi = 0; mi < 2; ++mi) {
                    asm volatile(
                        "mma.sync.aligned.m16n8k8.row.col.f32.tf32.tf32.f32 "
                        "{%0,%1,%2,%3}, {%4,%5,%6,%7}, {%8,%9}, {%0,%1,%2,%3};\n"
                        : "+f"(acc[mi][ni][0]), "+f"(acc[mi][ni][1]),
                          "+f"(acc[mi][ni][2]), "+f"(acc[mi][ni][3])
                        : "r"(a[mi][0]), "r"(a[mi][1]), "r"(a[mi][2]), "r"(a[mi][3]),
                          "r"(b0), "r"(b1));
                }
            }
        }
    }

    // Epilogue: bias + relu, write Y
    int jb = jt * 128 + wj * 32 + (lane >> 2);
    int rb = rt * 128 + wr * 64 + (lane & 3) * 2;
    #pragma unroll
    for (int mi = 0; mi < 2; ++mi) {
        int j0 = jb + mi * 16;
        float bb0 = bias[j0];
        float bb1 = bias[j0 + 8];
        #pragma unroll
        for (int ni = 0; ni < 8; ++ni) {
            int r0 = rb + ni * 8;
            g_Y[(size_t)j0 * RPAD + r0    ]       = fmaxf(acc[mi][ni][0] + bb0, 0.f);
            g_Y[(size_t)j0 * RPAD + r0 + 1]       = fmaxf(acc[mi][ni][1] + bb0, 0.f);
            g_Y[(size_t)(j0 + 8) * RPAD + r0    ] = fmaxf(acc[mi][ni][2] + bb1, 0.f);
            g_Y[(size_t)(j0 + 8) * RPAD + r0 + 1] = fmaxf(acc[mi][ni][3] + bb1, 0.f);
        }
    }
}

// ---------------------------------------------------------------------------
// Kernel 4: per-j epilogue.
//   mixed[0,k]    = (k%7==0)          (row sum 9)
//   mixed[i,0]    = (i%7==0), i>=1
//   mixed[1+7c+n, 1+q] = Y[j, (7*(7-c)+q)*7 + n]   (already relu'd)
//   d[i] = rsqrt(max(rowsum,1));  out = d[i]*mixed*d[k]
// ---------------------------------------------------------------------------
__global__ void __launch_bounds__(128) epi_k(float* __restrict__ out) {
    __shared__ float ys[RDIM + 1];
    __shared__ float dsh[NN];
    int j = blockIdx.x;
    int tid = threadIdx.x;

    const float* Yj = g_Y + (size_t)j * RPAD;
    for (int i = tid; i < RDIM; i += 128) ys[i] = Yj[i];
    __syncthreads();

    if (tid < 56) {
        int c = tid / 7;
        int n = tid - c * 7;
        int w = 7 * (7 - c);
        float s = (n == 6) ? 1.f : 0.f;
        #pragma unroll
        for (int q = 0; q < 56; ++q) s += ys[(w + q) * 7 + n];
        dsh[1 + tid] = rsqrtf(fmaxf(s, 1.f));
    } else if (tid == 56) {
        dsh[0] = rsqrtf(9.f);
    }
    __syncthreads();

    float* oj = out + (size_t)j * OUT_PER_J;
    for (int e = tid; e < OUT_PER_J; e += 128) {
        int i = e / 57;
        int k = e - i * 57;
        float v;
        if (i == 0) {
            v = (k % 7 == 0) ? dsh[0] * dsh[k] : 0.f;
        } else if (k == 0) {
            v = (i % 7 == 0) ? dsh[i] * dsh[0] : 0.f;
        } else {
            int c = (i - 1) / 7;
            int n = (i - 1) - c * 7;
            v = dsh[i] * dsh[k] * ys[(7 * (7 - c) + (k - 1)) * 7 + n];
        }
        oj[e] = v;
    }
}

// ---------------------------------------------------------------------------
extern "C" void kernel_launch(void* const* d_in, const int* in_sizes, int n_in,
                              void* d_out, int out_size) {
    const float* mat = (const float*)d_in[0];   // (1024,7,7)
    const float* te  = (const float*)d_in[1];   // (1024,15)
    const float* W   = (const float*)d_in[2];   // (8192,1024)
    const float* b   = (const float*)d_in[3];   // (8192,)
    float* out = (float*)d_out;                 // (8192,57,57)

    build_x<<<(RPAD * HB) / 256, 256>>>(mat, te);
    round_w<<<(HM * HB) / (4 * 256), 256>>>(W);
    gemm_k<<<dim3(6, 64), 256>>>(b);
    epi_k<<<HM, 128>>>(out);
}

// round 7
// speedup vs baseline: 1.2724x; 1.2724x over previous
#include <cuda_runtime.h>
#include <math.h>

#define HB 1024          // NUM_BASIC
#define HM 8192          // NUM_MIXED
#define TT 15            // 2*CLIP_LEN-1
#define RDIM 735         // TT*7*7
#define RPAD 768
#define NN 57
#define OUT_PER_J 3249   // 57*57

// Scratch (static device globals — allocation-free)
__device__ float g_X[RPAD * HB];   // X rows, tf32-rounded, padded rows zeroed
__device__ float g_W[HM * HB];     // W, tf32-rounded
__device__ float g_Y[HM * RPAD];   // relu(X @ W^T + b), per-j rows

__device__ __forceinline__ float to_tf32(float x) {
    unsigned u;
    asm("cvt.rna.tf32.f32 %0, %1;" : "=r"(u) : "f"(x));
    return __uint_as_float(u);
}

// ---------------------------------------------------------------------------
// Kernel 1: build X[r,h] = (1+sigmoid(te[h,t])) * relu(mat[h,n,m]), tf32-rounded
//   r = t*49 + m*7 + n
// ---------------------------------------------------------------------------
__global__ void build_x(const float* __restrict__ mat, const float* __restrict__ te) {
    int idx = blockIdx.x * 256 + threadIdx.x;
    int r = idx >> 10;
    int h = idx & 1023;
    float v = 0.f;
    if (r < RDIM) {
        int t = r / 49;
        int rem = r - t * 49;
        int m = rem / 7;
        int n = rem - m * 7;
        float a = mat[h * 49 + n * 7 + m];
        if (a > 0.f) {
            float s = 1.f + 1.f / (1.f + expf(-te[h * TT + t]));
            v = to_tf32(s * a);
        }
    }
    g_X[idx] = v;
}

// ---------------------------------------------------------------------------
// Kernel 2: round W to tf32 (RN) into scratch
// ---------------------------------------------------------------------------
__global__ void round_w(const float* __restrict__ W) {
    int idx = blockIdx.x * 256 + threadIdx.x;
    float4 v = reinterpret_cast<const float4*>(W)[idx];
    v.x = to_tf32(v.x);
    v.y = to_tf32(v.y);
    v.z = to_tf32(v.z);
    v.w = to_tf32(v.w);
    reinterpret_cast<float4*>(g_W)[idx] = v;
}

// ---------------------------------------------------------------------------
// Kernel 3: GEMM  Y[j, r] = relu( sum_h W[j,h]*X[r,h] + b[j] )
//   CTA 128x128, BK=32, 2-stage cp.async double buffer, dynamic smem.
//   8 warps: 4(j) x 2(r), warp tile 32x64, mma.sync m16n8k8 tf32.
// ---------------------------------------------------------------------------
#define TILE_F (128 * 36)         // floats per operand tile (padded stride 36)
#define STG_F  (2 * TILE_F)       // floats per stage (A + B)
#define SMEM_BYTES (2 * STG_F * 4)

__device__ __forceinline__ void issue_stage(float* sm, int s,
                                            const float* __restrict__ Wg,
                                            const float* __restrict__ Xg,
                                            int kc, int tid) {
    float* A = sm + s * STG_F;
    float* B = A + TILE_F;
    #pragma unroll
    for (int it = 0; it < 4; ++it) {
        int idx = tid + it * 256;          // 0..1023
        int row = idx >> 3;
        int col = (idx & 7) << 2;
        unsigned da = (unsigned)__cvta_generic_to_shared(&A[row * 36 + col]);
        unsigned db = (unsigned)__cvta_generic_to_shared(&B[row * 36 + col]);
        const float* ga = Wg + (size_t)row * HB + kc + col;
        const float* gb = Xg + (size_t)row * HB + kc + col;
        asm volatile("cp.async.cg.shared.global [%0], [%1], 16;\n" :: "r"(da), "l"(ga));
        asm volatile("cp.async.cg.shared.global [%0], [%1], 16;\n" :: "r"(db), "l"(gb));
    }
}

__global__ void __launch_bounds__(256, 2) gemm_k(const float* __restrict__ bias) {
    extern __shared__ float sm[];

    int tid  = threadIdx.x;
    int lane = tid & 31;
    int warp = tid >> 5;
    int wj = warp >> 1;             // 0..3
    int wr = warp & 1;              // 0..1
    int jt = blockIdx.y;            // 0..63
    int rt = blockIdx.x;            // 0..5

    const float* Wg = g_W + (size_t)(jt * 128) * HB;
    const float* Xg = g_X + (size_t)(rt * 128) * HB;

    float acc[2][8][4];
    #pragma unroll
    for (int mi = 0; mi < 2; ++mi)
        #pragma unroll
        for (int ni = 0; ni < 8; ++ni)
            #pragma unroll
            for (int e = 0; e < 4; ++e) acc[mi][ni][e] = 0.f;

    issue_stage(sm, 0, Wg, Xg, 0, tid);
    asm volatile("cp.async.commit_group;\n");

    const int NIT = HB / 32;   // 32
    for (int itk = 0; itk < NIT; ++itk) {
        int s = itk & 1;
        if (itk + 1 < NIT) {
            issue_stage(sm, s ^ 1, Wg, Xg, (itk + 1) * 32, tid);
            asm volatile("cp.async.commit_group;\n");
            asm volatile("cp.async.wait_group 1;\n");
        } else {
            asm volatile("cp.async.wait_group 0;\n");
        }
        __syncthreads();

        const float* A = sm + s * STG_F;
        const float* B = A + TILE_F;

        #pragma unroll
        for (int k8 = 0; k8 < 4; ++k8) {
            int kb = k8 * 8;
            int ar = wj * 32 + (lane >> 2);
            int ac = kb + (lane & 3);
            unsigned a[2][4];
            #pragma unroll
            for (int mi = 0; mi < 2; ++mi) {
                a[mi][0] = __float_as_uint(A[(ar + mi * 16    ) * 36 + ac    ]);
                a[mi][1] = __float_as_uint(A[(ar + mi * 16 + 8) * 36 + ac    ]);
                a[mi][2] = __float_as_uint(A[(ar + mi * 16    ) * 36 + ac + 4]);
                a[mi][3] = __float_as_uint(A[(ar + mi * 16 + 8) * 36 + ac + 4]);
            }
            int br = wr * 64 + (lane >> 2);
            #pragma unroll
            for (int ni = 0; ni < 8; ++ni) {
                unsigned b0 = __float_as_uint(B[(br + ni * 8) * 36 + ac    ]);
                unsigned b1 = __float_as_uint(B[(br + ni * 8) * 36 + ac + 4]);
                #pragma unroll
                for (int mi = 0; mi < 2; ++mi) {
                    asm volatile(
                        "mma.sync.aligned.m16n8k8.row.col.f32.tf32.tf32.f32 "
                        "{%0,%1,%2,%3}, {%4,%5,%6,%7}, {%8,%9}, {%0,%1,%2,%3};\n"
                        : "+f"(acc[mi][ni][0]), "+f"(acc[mi][ni][1]),
                          "+f"(acc[mi][ni][2]), "+f"(acc[mi][ni][3])
                        : "r"(a[mi][0]), "r"(a[mi][1]), "r"(a[mi][2]), "r"(a[mi][3]),
                          "r"(b0), "r"(b1));
                }
            }
        }
        __syncthreads();
    }

    // Epilogue: bias + relu, write Y
    int jb = jt * 128 + wj * 32 + (lane >> 2);
    int rb = rt * 128 + wr * 64 + (lane & 3) * 2;
    #pragma unroll
    for (int mi = 0; mi < 2; ++mi) {
        int j0 = jb + mi * 16;
        float bb0 = bias[j0];
        float bb1 = bias[j0 + 8];
        #pragma unroll
        for (int ni = 0; ni < 8; ++ni) {
            int r0 = rb + ni * 8;
            g_Y[(size_t)j0 * RPAD + r0    ]       = fmaxf(acc[mi][ni][0] + bb0, 0.f);
            g_Y[(size_t)j0 * RPAD + r0 + 1]       = fmaxf(acc[mi][ni][1] + bb0, 0.f);
            g_Y[(size_t)(j0 + 8) * RPAD + r0    ] = fmaxf(acc[mi][ni][2] + bb1, 0.f);
            g_Y[(size_t)(j0 + 8) * RPAD + r0 + 1] = fmaxf(acc[mi][ni][3] + bb1, 0.f);
        }
    }
}

// ---------------------------------------------------------------------------
// Kernel 4: per-j epilogue, division-free inner loop.
//   blockDim 224 = 4 rows x 56 cols. k' fixed per thread.
//   mixed[1+7c+n, 1+q] = Y[j, (7*(7-c)+q)*7 + n];  d = rsqrt(max(rowsum,1))
// ---------------------------------------------------------------------------
__global__ void __launch_bounds__(224) epi_k(float* __restrict__ out) {
    __shared__ float ys[RDIM];
    __shared__ float dsh[NN];
    __shared__ int   rbase[56];
    int j = blockIdx.x;
    int tid = threadIdx.x;

    const float* Yj = g_Y + (size_t)j * RPAD;
    for (int i = tid; i < RDIM; i += 224) ys[i] = Yj[i];
    __syncthreads();

    if (tid < 56) {
        int c = tid / 7;
        int n = tid - c * 7;
        int w = 7 * (7 - c);
        float s = (n == 6) ? 1.f : 0.f;
        #pragma unroll
        for (int q = 0; q < 56; ++q) s += ys[(w + q) * 7 + n];
        dsh[1 + tid] = rsqrtf(fmaxf(s, 1.f));
        rbase[tid] = w * 7 + n;
    } else if (tid == 56) {
        dsh[0] = rsqrtf(9.f);
    }
    __syncthreads();

    float* oj = out + (size_t)j * OUT_PER_J;
    int ro = tid / 56;              // 0..3  (computed once)
    int kp = tid - ro * 56;         // 0..55 (fixed per thread)
    float dk = dsh[1 + kp];
    int k7 = kp * 7;

    // main 56x56 block
    #pragma unroll
    for (int g = 0; g < 14; ++g) {
        int ip = ro + g * 4;        // 0..55
        float v = dsh[1 + ip] * dk * ys[rbase[ip] + k7];
        oj[(1 + ip) * 57 + 1 + kp] = v;
    }

    // boundary: row 0 (57 elems) and column 0 (rows 1..56)
    if (tid < 57) {
        float v0 = ((tid % 7) == 0) ? dsh[0] * dsh[tid] : 0.f;
        oj[tid] = v0;
    } else if (tid < 113) {
        int i = tid - 56;           // 1..56
        float v = ((i % 7) == 0) ? dsh[i] * dsh[0] : 0.f;
        oj[i * 57] = v;
    }
}

// ---------------------------------------------------------------------------
extern "C" void kernel_launch(void* const* d_in, const int* in_sizes, int n_in,
                              void* d_out, int out_size) {
    const float* mat = (const float*)d_in[0];   // (1024,7,7)
    const float* te  = (const float*)d_in[1];   // (1024,15)
    const float* W   = (const float*)d_in[2];   // (8192,1024)
    const float* b   = (const float*)d_in[3];   // (8192,)
    float* out = (float*)d_out;                 // (8192,57,57)

    cudaFuncSetAttribute(gemm_k, cudaFuncAttributeMaxDynamicSharedMemorySize, SMEM_BYTES);

    build_x<<<(RPAD * HB) / 256, 256>>>(mat, te);
    round_w<<<(HM * HB) / (4 * 256), 256>>>(W);
    gemm_k<<<dim3(6, 64), 256, SMEM_BYTES>>>(b);
    epi_k<<<HM, 224>>>(out);
}